// round 1
// baseline (speedup 1.0000x reference)
#include <cuda_runtime.h>
#include <cuda_bf16.h>

// Problem constants
#define B_  16
#define C_  4096
#define HD_ 1024   // H*D = 16*64
#define F_  1024

// Scratch: bf16-rounded selected v vectors, stored as f32 for the f32 GEMM.
__device__ float g_vsel[B_ * HD_];

// ---------------------------------------------------------------------------
// Kernel A: per batch, pick the v vector that attention degenerates to.
//   start = 0 if idx+1 <= C else (idx+1) % C
//   if start == idx % C  (only idx==0): v_sel = x @ wv + bv   (fresh write)
//   else:                               v_sel = kv_value[b, start]
// Round to bf16 (attention output dtype), store back as f32.
// ---------------------------------------------------------------------------
__global__ void select_v_kernel(const float* __restrict__ x,
                                const int*   __restrict__ kv_idx,
                                const float* __restrict__ kv_value,
                                const float* __restrict__ wv,
                                const float* __restrict__ bv)
{
    const int b = blockIdx.x;
    const int idx = kv_idx[b];
    const int new_idx = idx + 1;
    const int start = (new_idx <= C_) ? 0 : (new_idx % C_);
    const bool use_new = (start == (idx % C_));

    if (!use_new) {
        const float* src = kv_value + ((size_t)b * C_ + start) * HD_;
        for (int j = threadIdx.x; j < HD_; j += blockDim.x) {
            g_vsel[b * HD_ + j] = __bfloat162float(__float2bfloat16(src[j]));
        }
    } else {
        __shared__ float xs[F_];
        for (int f = threadIdx.x; f < F_; f += blockDim.x)
            xs[f] = x[b * F_ + f];
        __syncthreads();
        for (int j = threadIdx.x; j < HD_; j += blockDim.x) {
            float acc = bv[j];
            #pragma unroll 8
            for (int f = 0; f < F_; f++)
                acc = fmaf(xs[f], wv[(size_t)f * HD_ + j], acc);
            g_vsel[b * HD_ + j] = __bfloat162float(__float2bfloat16(acc));
        }
    }
}

// ---------------------------------------------------------------------------
// Kernel B: initialize y[b,f] = bo[f] (output is poisoned to 0xAA by harness).
// ---------------------------------------------------------------------------
__global__ void init_out_kernel(float* __restrict__ y,
                                const float* __restrict__ bo)
{
    int i = blockIdx.x * blockDim.x + threadIdx.x;
    if (i < B_ * F_) y[i] = bo[i & (F_ - 1)];
}

// ---------------------------------------------------------------------------
// Kernel C: y[b,f] += sum_hd vsel[b,hd] * wo[hd,f]  (split-K with atomics)
//   grid = (F/TF, HD/TK), block = TF threads, each thread owns one f.
//   wo layout [H,D,F]: wo[hd,f] at hd*F + f  -> coalesced across threads.
// ---------------------------------------------------------------------------
#define TF 128
#define TK 64

__global__ void gemm_splitk_kernel(const float* __restrict__ wo,
                                   float* __restrict__ y)
{
    const int f  = blockIdx.x * TF + threadIdx.x;
    const int k0 = blockIdx.y * TK;

    __shared__ float vs[B_][TK];
    for (int i = threadIdx.x; i < B_ * TK; i += TF) {
        int b = i / TK, k = i % TK;
        vs[b][k] = g_vsel[b * HD_ + k0 + k];
    }
    __syncthreads();

    float acc[B_];
    #pragma unroll
    for (int b = 0; b < B_; b++) acc[b] = 0.0f;

    #pragma unroll 4
    for (int k = 0; k < TK; k++) {
        float w = wo[(size_t)(k0 + k) * F_ + f];
        #pragma unroll
        for (int b = 0; b < B_; b++)
            acc[b] = fmaf(vs[b][k], w, acc[b]);
    }

    #pragma unroll
    for (int b = 0; b < B_; b++)
        atomicAdd(&y[b * F_ + f], acc[b]);
}

// ---------------------------------------------------------------------------
// Launch. Input order (metadata): x, mask, kv_idx, kv_key, kv_value,
// wq, bq, wk, bk, wv, bv, wo, bo
// ---------------------------------------------------------------------------
extern "C" void kernel_launch(void* const* d_in, const int* in_sizes, int n_in,
                              void* d_out, int out_size)
{
    const float* x        = (const float*)d_in[0];
    const int*   kv_idx   = (const int*)  d_in[2];
    const float* kv_value = (const float*)d_in[4];
    const float* wv       = (const float*)d_in[9];
    const float* bv       = (const float*)d_in[10];
    const float* wo       = (const float*)d_in[11];
    const float* bo       = (const float*)d_in[12];
    float* y = (float*)d_out;

    select_v_kernel<<<B_, 256>>>(x, kv_idx, kv_value, wv, bv);
    init_out_kernel<<<(B_ * F_ + 255) / 256, 256>>>(y, bo);
    gemm_splitk_kernel<<<dim3(F_ / TF, HD_ / TK), TF>>>(wo, y);
}